// round 5
// baseline (speedup 1.0000x reference)
#include <cuda_runtime.h>
#include <cuda_fp16.h>
#include <cstdint>

// ---------------------------------------------------------------- constants
#define A_DIM    2048
#define D_DIM    128
#define O_DIM    128
#define F_DIM    16
#define KBIG     (A_DIM * F_DIM)      // 32768; k = b*16 + f (contiguous in conn)
#define FILT_ROW 2080                 // 16 * 130
#define KSPLIT   8
#define KC       (KBIG / KSPLIT)      // 4096
#define KT       64                   // k-depth per ktile in k_big
#define ITERS    (KC / KT)            // 64

// swizzles: XOR 16B-segment bits with row-low bits
#define SWZ128(x) ((x) ^ (((x) >> 3) & 0x70))   // 128B rows
#define SWZ256(x) ((x) ^ (((x) >> 4) & 0xF0))   // 256B rows

// k_big smem: A16 double buffer (2 x 16KB) + B ring (4 x 16KB)
#define BIG_SMEM   (2 * 16384 + 4 * 16384)      // 98304
// k_wbuild smem: A 64KB + B 32KB (epilogue staging 69632 reuses)
#define WB_SMEM    98304

// scratch (__device__ globals: allocation-free rule)
__device__ __half g_Wh[(size_t)KBIG * O_DIM];            // W[k][o] fp16, 8 MB
__device__ __half g_nodeh[(size_t)A_DIM * D_DIM];        // node fp16
__device__ __half g_G[(size_t)D_DIM * A_DIM];            // G[d][f*128+o] = filt[o,f,d]
__device__ float  g_part[(size_t)KSPLIT * A_DIM * O_DIM];

// ---------------------------------------------------------------- ptx utils
__device__ __forceinline__ void cpa16s(uint32_t dst, const void* src) {
    asm volatile("cp.async.cg.shared.global [%0], [%1], 16;" :: "r"(dst), "l"(src));
}
__device__ __forceinline__ void cp_commit() { asm volatile("cp.async.commit_group;"); }
__device__ __forceinline__ void cp_wait0()  { asm volatile("cp.async.wait_group 0;"); }
__device__ __forceinline__ void cp_wait2()  { asm volatile("cp.async.wait_group 2;"); }

__device__ __forceinline__ void ldm_x4(uint32_t* r, uint32_t a) {
    asm volatile("ldmatrix.sync.aligned.m8n8.x4.shared.b16 {%0,%1,%2,%3}, [%4];"
        : "=r"(r[0]), "=r"(r[1]), "=r"(r[2]), "=r"(r[3]) : "r"(a));
}
__device__ __forceinline__ void ldm_x4t(uint32_t* r, uint32_t a) {
    asm volatile("ldmatrix.sync.aligned.m8n8.x4.trans.shared.b16 {%0,%1,%2,%3}, [%4];"
        : "=r"(r[0]), "=r"(r[1]), "=r"(r[2]), "=r"(r[3]) : "r"(a));
}
__device__ __forceinline__ void mma16(float* d, const uint32_t* a, const uint32_t* b) {
    asm volatile(
        "mma.sync.aligned.m16n8k16.row.col.f32.f16.f16.f32 "
        "{%0,%1,%2,%3}, {%4,%5,%6,%7}, {%8,%9}, {%0,%1,%2,%3};"
        : "+f"(d[0]), "+f"(d[1]), "+f"(d[2]), "+f"(d[3])
        : "r"(a[0]), "r"(a[1]), "r"(a[2]), "r"(a[3]), "r"(b[0]), "r"(b[1]));
}
__device__ __forceinline__ uint32_t pack_h2(float x, float y) {
    __half2 h = __floats2half2_rn(x, y);
    return *reinterpret_cast<uint32_t*>(&h);
}

// ---------------------------------------------------------------------------
// k_prep: build g_G[d][f*128+o] = filt[o,f,d] (fp16) and g_nodeh = fp16(node)
// blocks 0..15: filt transpose (one f each); blocks 16..271: node convert.
// ---------------------------------------------------------------------------
__global__ void __launch_bounds__(256) k_prep(const float* __restrict__ node,
                                              const float* __restrict__ filt) {
    __shared__ float sm[128][65];
    const int t = threadIdx.x;

    if (blockIdx.x < 16) {
        const int f = blockIdx.x;
        #pragma unroll
        for (int p = 0; p < 2; p++) {      // d-halves of 64
            const int o  = t >> 1;
            const int dq = (t & 1) * 32;
            const float* src = filt + (size_t)o * FILT_ROW + f * 130 + p * 64 + dq;
            #pragma unroll
            for (int q = 0; q < 16; q++) {
                float2 v = *reinterpret_cast<const float2*>(src + q * 2);
                sm[o][dq + q * 2]     = v.x;
                sm[o][dq + q * 2 + 1] = v.y;
            }
            __syncthreads();
            const int dl = t & 63, op = t >> 6;        // d-local, o-part (32 o's)
            uint32_t* dst = reinterpret_cast<uint32_t*>(
                g_G + (size_t)(p * 64 + dl) * A_DIM + f * 128 + op * 32);
            #pragma unroll
            for (int q = 0; q < 16; q++)
                dst[q] = pack_h2(sm[op * 32 + q * 2][dl], sm[op * 32 + q * 2 + 1][dl]);
            __syncthreads();
        }
    } else {
        const int idx = (blockIdx.x - 16) * 256 + t;   // over 65536 float4
        float4 v = reinterpret_cast<const float4*>(node)[idx];
        reinterpret_cast<uint2*>(g_nodeh)[idx] =
            make_uint2(pack_h2(v.x, v.y), pack_h2(v.z, v.w));
    }
}

// ---------------------------------------------------------------------------
// k_wbuild: g_Wh[b*2048 + fo] = sum_d node_h[b,d] * G[d, fo]
// One fp16 GEMM M=2048(b) x N=2048(fo) x K=128. CTA 256x128, 8 warps (64x64).
// grid = (8 b-tiles, 16 fo-tiles). Single-shot SMEM load (K=128 fits).
// ---------------------------------------------------------------------------
__global__ void __launch_bounds__(256, 1) k_wbuild() {
    extern __shared__ char smc[];
    const uint32_t sb = (uint32_t)__cvta_generic_to_shared(smc);
    const int t = threadIdx.x, lane = t & 31, wid = t >> 5;
    const int wm = wid >> 1, wn = wid & 1;
    const int b0  = blockIdx.x * 256;
    const int fo0 = blockIdx.y * 128;

    // load A: node_h[b0..b0+255][0..127] -> smem[0..64KB), rows 256B, SWZ256
    #pragma unroll
    for (int q = 0; q < 16; q++) {
        int c = q * 256 + t;                 // 0..4095 segments
        int m = c >> 4, seg = c & 15;
        cpa16s(sb + SWZ256(m * 256 + seg * 16),
               g_nodeh + (size_t)(b0 + m) * D_DIM + seg * 8);
    }
    // load B: G[0..127][fo0..fo0+127] -> smem[64KB..96KB), rows 256B, SWZ256
    #pragma unroll
    for (int q = 0; q < 8; q++) {
        int c = q * 256 + t;                 // 0..2047
        int d = c >> 4, seg = c & 15;
        cpa16s(sb + 65536 + SWZ256(d * 256 + seg * 16),
               g_G + (size_t)d * A_DIM + fo0 + seg * 8);
    }
    cp_commit();
    cp_wait0();
    __syncthreads();

    float acc[4][8][4];
    #pragma unroll
    for (int i = 0; i < 4; i++)
        #pragma unroll
        for (int j = 0; j < 8; j++)
            #pragma unroll
            for (int q = 0; q < 4; q++) acc[i][j][q] = 0.f;

    const int aRow = wm * 64 + (lane & 7) + ((lane >> 3) & 1) * 8;
    const int aKb  = ((lane >> 4) & 1) * 16;
    const int bK   = (lane & 7) + ((lane >> 3) & 1) * 8;
    const int bNb  = (wn * 64 + ((lane >> 4) & 1) * 8) * 2;

    #pragma unroll
    for (int kc = 0; kc < 8; kc++) {
        uint32_t a[4][4], b[4][4];
        #pragma unroll
        for (int i = 0; i < 4; i++)
            ldm_x4(a[i], sb + SWZ256((aRow + i * 16) * 256 + kc * 32 + aKb));
        #pragma unroll
        for (int jj = 0; jj < 4; jj++)
            ldm_x4t(b[jj], sb + 65536 + SWZ256((kc * 16 + bK) * 256 + bNb + jj * 32));
        #pragma unroll
        for (int i = 0; i < 4; i++)
            #pragma unroll
            for (int jj = 0; jj < 4; jj++) {
                mma16(acc[i][jj * 2],     a[i], &b[jj][0]);
                mma16(acc[i][jj * 2 + 1], a[i], &b[jj][2]);
            }
    }

    // stage D (fp16) through smem, then coalesced stores
    __syncthreads();
    __half* tile = reinterpret_cast<__half*>(smc);      // [256][136]
    #pragma unroll
    for (int i = 0; i < 4; i++)
        #pragma unroll
        for (int j = 0; j < 8; j++) {
            const int m = wm * 64 + i * 16 + (lane >> 2);
            const int n = wn * 64 + j * 8 + (lane & 3) * 2;
            *reinterpret_cast<uint32_t*>(tile + m * 136 + n) =
                pack_h2(acc[i][j][0], acc[i][j][1]);
            *reinterpret_cast<uint32_t*>(tile + (m + 8) * 136 + n) =
                pack_h2(acc[i][j][2], acc[i][j][3]);
        }
    __syncthreads();
    {
        // FIX (R4 bug): cover ALL 256 rows — one full row (128 halfs) per thread.
        const int m = t;                               // 0..255
        __half* dst = g_Wh + (size_t)(b0 + m) * A_DIM + fo0;
        const __half* src = tile + m * 136;            // 272B row pitch, 16B-aligned
        #pragma unroll
        for (int q = 0; q < 16; q++)
            *reinterpret_cast<uint4*>(dst + q * 8) =
                *reinterpret_cast<const uint4*>(src + q * 8);
    }
}

// ---------------------------------------------------------------------------
// k_big: part[s][a,o] = sum_{k in split s} conn2d[a,k] * Wh[k,o]
// fp16 MMA; A converted in-flight (LDG fp32 -> cvt -> swizzled STS).
// CTA 128x128, KT=64, 8 warps (32m x 64n). grid = (16 m-tiles, KSPLIT).
// ---------------------------------------------------------------------------
__global__ void __launch_bounds__(256, 1) k_big(const float* __restrict__ conn) {
    extern __shared__ char smc[];
    const uint32_t sb = (uint32_t)__cvta_generic_to_shared(smc);
    const int t = threadIdx.x, lane = t & 31, wid = t >> 5;
    const int wm = wid >> 1, wn = wid & 1;
    const int m0    = blockIdx.x * 128;
    const int kbase = blockIdx.y * KC;

    // smem: A16[2] at 0/16384 ; B[4] at 32768 + s*16384
    const float* aSrcBase = conn + (size_t)(m0 + (t >> 1)) * KBIG + kbase + (t & 1) * 32;
    const uint32_t aStsBase = (t >> 1) * 128 + (t & 1) * 64;

    auto cpB = [&](int it) {
        if (it < ITERS) {
            const uint32_t bb = sb + 32768 + (it & 3) * 16384;
            const __half* src = g_Wh + (size_t)(kbase + it * KT) * O_DIM;
            #pragma unroll
            for (int q = 0; q < 4; q++) {
                int c = q * 256 + t;           // 0..1023
                int k = c >> 4, seg = c & 15;
                cpa16s(bb + SWZ256(k * 256 + seg * 16), src + k * O_DIM + seg * 8);
            }
        }
        cp_commit();
    };

    float4 rA[2][8];
    auto ldgA = [&](int it) {
        if (it < ITERS) {
            const float4* src = reinterpret_cast<const float4*>(aSrcBase + it * KT);
            #pragma unroll
            for (int q = 0; q < 8; q++) rA[it & 1][q] = src[q];
        }
    };
    auto cvtA = [&](int it) {
        if (it < ITERS) {
            char* ab = smc + (it & 1) * 16384;
            const float4* r = rA[it & 1];
            #pragma unroll
            for (int q = 0; q < 8; q++)
                *reinterpret_cast<uint2*>(ab + SWZ128(aStsBase + q * 8)) =
                    make_uint2(pack_h2(r[q].x, r[q].y), pack_h2(r[q].z, r[q].w));
        }
    };

    // prologue
    cpB(0); cpB(1); cpB(2);
    ldgA(0); ldgA(1);
    cvtA(0);

    float acc[2][8][4];
    #pragma unroll
    for (int i = 0; i < 2; i++)
        #pragma unroll
        for (int j = 0; j < 8; j++)
            #pragma unroll
            for (int q = 0; q < 4; q++) acc[i][j][q] = 0.f;

    const int aRow = wm * 32 + (lane & 7) + ((lane >> 3) & 1) * 8;
    const int aKb  = ((lane >> 4) & 1) * 16;
    const int bK   = (lane & 7) + ((lane >> 3) & 1) * 8;
    const int bNb  = (wn * 64 + ((lane >> 4) & 1) * 8) * 2;

    for (int it = 0; it < ITERS; ++it) {
        cp_wait2();                 // B[it] arrived
        __syncthreads();            // B[it] + A16[it&1] visible; B[(it+3)&3] free
        cpB(it + 3);
        ldgA(it + 2);

        const uint32_t ab = sb + (it & 1) * 16384;
        const uint32_t bb = sb + 32768 + (it & 3) * 16384;
        #pragma unroll
        for (int kc = 0; kc < 4; kc++) {
            uint32_t a[2][4], b[4][4];
            ldm_x4(a[0], ab + SWZ128((aRow) * 128 + kc * 32 + aKb));
            ldm_x4(a[1], ab + SWZ128((aRow + 16) * 128 + kc * 32 + aKb));
            #pragma unroll
            for (int jj = 0; jj < 4; jj++)
                ldm_x4t(b[jj], bb + SWZ256((kc * 16 + bK) * 256 + bNb + jj * 32));
            #pragma unroll
            for (int i = 0; i < 2; i++)
                #pragma unroll
                for (int jj = 0; jj < 4; jj++) {
                    mma16(acc[i][jj * 2],     a[i], &b[jj][0]);
                    mma16(acc[i][jj * 2 + 1], a[i], &b[jj][2]);
                }
        }
        cvtA(it + 1);
    }

    float* dst = g_part + (size_t)blockIdx.y * (A_DIM * O_DIM);
    #pragma unroll
    for (int i = 0; i < 2; i++)
        #pragma unroll
        for (int j = 0; j < 8; j++) {
            const int r0  = m0 + wm * 32 + i * 16 + (lane >> 2);
            const int col = wn * 64 + j * 8 + (lane & 3) * 2;
            *reinterpret_cast<float2*>(dst + (size_t)r0 * O_DIM + col) =
                make_float2(acc[i][j][0], acc[i][j][1]);
            *reinterpret_cast<float2*>(dst + (size_t)(r0 + 8) * O_DIM + col) =
                make_float2(acc[i][j][2], acc[i][j][3]);
        }
}

// ---------------------------------------------------------------------------
// k_reduce: out = sum_s part[s] + bond-term   (deterministic fp32)
// ---------------------------------------------------------------------------
__global__ void __launch_bounds__(256) k_reduce(const float* __restrict__ bond,
                                                const float* __restrict__ filt,
                                                float* __restrict__ out) {
    const int idx = blockIdx.x * 256 + threadIdx.x;   // a*128 + o
    const int a = idx >> 7;
    const int o = idx & 127;

    float s = 0.f;
    #pragma unroll
    for (int sp = 0; sp < KSPLIT; sp++)
        s += g_part[(size_t)sp * (A_DIM * O_DIM) + idx];

    #pragma unroll
    for (int f = 0; f < F_DIM; f++) {
        s += bond[a * (F_DIM * 2) + 2 * f + 0] * filt[o * FILT_ROW + f * 130 + 128];
        s += bond[a * (F_DIM * 2) + 2 * f + 1] * filt[o * FILT_ROW + f * 130 + 129];
    }
    out[idx] = s;
}

// ---------------------------------------------------------------------------
extern "C" void kernel_launch(void* const* d_in, const int* in_sizes, int n_in,
                              void* d_out, int out_size) {
    const float* node = (const float*)d_in[0];   // (2048, 128)
    const float* conn = (const float*)d_in[1];   // (2048, 2048, 16)
    const float* bond = (const float*)d_in[2];   // (2048, 16, 2)
    const float* filt = (const float*)d_in[3];   // (128, 16, 130)
    float* out = (float*)d_out;                  // (2048, 128)
    (void)in_sizes; (void)n_in; (void)out_size;

    cudaFuncSetAttribute(k_wbuild, cudaFuncAttributeMaxDynamicSharedMemorySize, WB_SMEM);
    cudaFuncSetAttribute(k_big,    cudaFuncAttributeMaxDynamicSharedMemorySize, BIG_SMEM);

    k_prep<<<272, 256>>>(node, filt);
    k_wbuild<<<dim3(A_DIM / 256, A_DIM / 128), 256, WB_SMEM>>>();
    k_big<<<dim3(A_DIM / 128, KSPLIT), 256, BIG_SMEM>>>(conn);
    k_reduce<<<(A_DIM * O_DIM) / 256, 256>>>(bond, filt, out);
}

// round 6
// speedup vs baseline: 1.5026x; 1.5026x over previous
#include <cuda_runtime.h>
#include <cuda_fp16.h>
#include <cstdint>

// ---------------------------------------------------------------- constants
#define A_DIM    2048
#define D_DIM    128
#define O_DIM    128
#define F_DIM    16
#define KBIG     (A_DIM * F_DIM)      // 32768; k = b*16 + f (contiguous in conn)
#define FILT_ROW 2080                 // 16 * 130
#define KSPLIT   8
#define KC       (KBIG / KSPLIT)      // 4096
#define KT       64                   // k-depth per ktile in k_big
#define ITERS    (KC / KT)            // 64

#define SWZ128(x) ((x) ^ (((x) >> 3) & 0x70))   // 128B rows: seg bits4-6 ^= row bits7-9
#define SWZ256(x) ((x) ^ (((x) >> 4) & 0xF0))   // 256B rows: seg bits4-7 ^= row bits8-11

// k_big smem: A16 double buffer (2x16KB) + B ring (4x16KB) + 4 mbarriers
#define BIG_SMEM   (98304 + 64)
#define WB_SMEM    98304

// scratch (__device__ globals: allocation-free rule)
// g_Wh stored TILED+SWIZZLED: tile g = k/64 (16KB each), within tile byte
// offset = SWZ256((k&63)*256 + o*2) — exactly what k_big's B-stage wants.
__device__ __half g_Wh[(size_t)KBIG * O_DIM];            // 8 MB
__device__ __half g_nodeh[(size_t)A_DIM * D_DIM];        // node fp16
__device__ __half g_G[(size_t)D_DIM * A_DIM];            // G[d][f*128+o] = filt[o,f,d]
__device__ float  g_bias[32 * 128];                      // bias[fj][o] = filt[o,f,128+j]
__device__ float  g_part[(size_t)KSPLIT * A_DIM * O_DIM];

// ---------------------------------------------------------------- ptx utils
__device__ __forceinline__ void cpa16s(uint32_t dst, const void* src) {
    asm volatile("cp.async.cg.shared.global [%0], [%1], 16;" :: "r"(dst), "l"(src));
}
__device__ __forceinline__ void cp_commit() { asm volatile("cp.async.commit_group;"); }
__device__ __forceinline__ void cp_wait0()  { asm volatile("cp.async.wait_group 0;"); }

__device__ __forceinline__ void mbar_init(uint32_t a, uint32_t cnt) {
    asm volatile("mbarrier.init.shared.b64 [%0], %1;" :: "r"(a), "r"(cnt) : "memory");
}
__device__ __forceinline__ void mbar_expect_tx(uint32_t a, uint32_t bytes) {
    asm volatile("mbarrier.arrive.expect_tx.shared.b64 _, [%0], %1;"
                 :: "r"(a), "r"(bytes) : "memory");
}
__device__ __forceinline__ void mbar_wait(uint32_t a, uint32_t parity) {
    asm volatile(
        "{\n"
        ".reg .pred P;\n"
        "LW%=:\n"
        "mbarrier.try_wait.parity.acquire.cta.shared::cta.b64 P, [%0], %1, 0x989680;\n"
        "@P bra LD%=;\n"
        "bra LW%=;\n"
        "LD%=:\n"
        "}" :: "r"(a), "r"(parity) : "memory");
}
__device__ __forceinline__ void bulk_g2s(uint32_t dst, const void* src,
                                         uint32_t bytes, uint32_t mbar) {
    asm volatile(
        "cp.async.bulk.shared::cluster.global.mbarrier::complete_tx::bytes "
        "[%0], [%1], %2, [%3];"
        :: "r"(dst), "l"(src), "r"(bytes), "r"(mbar) : "memory");
}

__device__ __forceinline__ void ldm_x4(uint32_t* r, uint32_t a) {
    asm volatile("ldmatrix.sync.aligned.m8n8.x4.shared.b16 {%0,%1,%2,%3}, [%4];"
        : "=r"(r[0]), "=r"(r[1]), "=r"(r[2]), "=r"(r[3]) : "r"(a));
}
__device__ __forceinline__ void ldm_x4t(uint32_t* r, uint32_t a) {
    asm volatile("ldmatrix.sync.aligned.m8n8.x4.trans.shared.b16 {%0,%1,%2,%3}, [%4];"
        : "=r"(r[0]), "=r"(r[1]), "=r"(r[2]), "=r"(r[3]) : "r"(a));
}
__device__ __forceinline__ void mma16(float* d, const uint32_t* a, const uint32_t* b) {
    asm volatile(
        "mma.sync.aligned.m16n8k16.row.col.f32.f16.f16.f32 "
        "{%0,%1,%2,%3}, {%4,%5,%6,%7}, {%8,%9}, {%0,%1,%2,%3};"
        : "+f"(d[0]), "+f"(d[1]), "+f"(d[2]), "+f"(d[3])
        : "r"(a[0]), "r"(a[1]), "r"(a[2]), "r"(a[3]), "r"(b[0]), "r"(b[1]));
}
__device__ __forceinline__ uint32_t pack_h2(float x, float y) {
    __half2 h = __floats2half2_rn(x, y);
    return *reinterpret_cast<uint32_t*>(&h);
}

// ---------------------------------------------------------------------------
// k_prep: g_G[d][f*128+o]=filt[o,f,d] fp16; g_nodeh=fp16(node); g_bias extract.
// ---------------------------------------------------------------------------
__global__ void __launch_bounds__(256) k_prep(const float* __restrict__ node,
                                              const float* __restrict__ filt) {
    __shared__ float sm[128][65];
    const int t = threadIdx.x;

    if (blockIdx.x < 16) {
        const int f = blockIdx.x;
        // bias slice: bias[f*2+j][o]
        {
            const int o = t >> 1, j = t & 1;
            g_bias[f * 256 + j * 128 + o] = filt[(size_t)o * FILT_ROW + f * 130 + 128 + j];
        }
        #pragma unroll
        for (int p = 0; p < 2; p++) {      // d-halves of 64
            const int o  = t >> 1;
            const int dq = (t & 1) * 32;
            const float* src = filt + (size_t)o * FILT_ROW + f * 130 + p * 64 + dq;
            #pragma unroll
            for (int q = 0; q < 16; q++) {
                float2 v = *reinterpret_cast<const float2*>(src + q * 2);
                sm[o][dq + q * 2]     = v.x;
                sm[o][dq + q * 2 + 1] = v.y;
            }
            __syncthreads();
            const int dl = t & 63, op = t >> 6;
            uint32_t* dst = reinterpret_cast<uint32_t*>(
                g_G + (size_t)(p * 64 + dl) * A_DIM + f * 128 + op * 32);
            #pragma unroll
            for (int q = 0; q < 16; q++)
                dst[q] = pack_h2(sm[op * 32 + q * 2][dl], sm[op * 32 + q * 2 + 1][dl]);
            __syncthreads();
        }
    } else {
        const int idx = (blockIdx.x - 16) * 256 + t;   // over 65536 float4
        float4 v = reinterpret_cast<const float4*>(node)[idx];
        reinterpret_cast<uint2*>(g_nodeh)[idx] =
            make_uint2(pack_h2(v.x, v.y), pack_h2(v.z, v.w));
    }
}

// ---------------------------------------------------------------------------
// k_wbuild: W[k=b*16+f][o] = sum_d node_h[b,d] * G[d, f*128+o]
// GEMM M=2048(b) x N=2048(fo) x K=128. CTA 256x128, 8 warps (64x64).
// Output written in k_big's TILED+SWIZZLED g_Wh layout.
// ---------------------------------------------------------------------------
__global__ void __launch_bounds__(256, 1) k_wbuild() {
    extern __shared__ char smc[];
    const uint32_t sb = (uint32_t)__cvta_generic_to_shared(smc);
    const int t = threadIdx.x, lane = t & 31, wid = t >> 5;
    const int wm = wid >> 1, wn = wid & 1;
    const int b0  = blockIdx.x * 256;
    const int fo0 = blockIdx.y * 128;
    const int f   = blockIdx.y;          // fo0 == f*128

    #pragma unroll
    for (int q = 0; q < 16; q++) {
        int c = q * 256 + t;
        int m = c >> 4, seg = c & 15;
        cpa16s(sb + SWZ256(m * 256 + seg * 16),
               g_nodeh + (size_t)(b0 + m) * D_DIM + seg * 8);
    }
    #pragma unroll
    for (int q = 0; q < 8; q++) {
        int c = q * 256 + t;
        int d = c >> 4, seg = c & 15;
        cpa16s(sb + 65536 + SWZ256(d * 256 + seg * 16),
               g_G + (size_t)d * A_DIM + fo0 + seg * 8);
    }
    cp_commit();
    cp_wait0();
    __syncthreads();

    float acc[4][8][4];
    #pragma unroll
    for (int i = 0; i < 4; i++)
        #pragma unroll
        for (int j = 0; j < 8; j++)
            #pragma unroll
            for (int q = 0; q < 4; q++) acc[i][j][q] = 0.f;

    const int aRow = wm * 64 + (lane & 7) + ((lane >> 3) & 1) * 8;
    const int aKb  = ((lane >> 4) & 1) * 16;
    const int bK   = (lane & 7) + ((lane >> 3) & 1) * 8;
    const int bNb  = (wn * 64 + ((lane >> 4) & 1) * 8) * 2;

    #pragma unroll
    for (int kc = 0; kc < 8; kc++) {
        uint32_t a[4][4], b[4][4];
        #pragma unroll
        for (int i = 0; i < 4; i++)
            ldm_x4(a[i], sb + SWZ256((aRow + i * 16) * 256 + kc * 32 + aKb));
        #pragma unroll
        for (int jj = 0; jj < 4; jj++)
            ldm_x4t(b[jj], sb + 65536 + SWZ256((kc * 16 + bK) * 256 + bNb + jj * 32));
        #pragma unroll
        for (int i = 0; i < 4; i++)
            #pragma unroll
            for (int jj = 0; jj < 4; jj++) {
                mma16(acc[i][jj * 2],     a[i], &b[jj][0]);
                mma16(acc[i][jj * 2 + 1], a[i], &b[jj][2]);
            }
    }

    __syncthreads();
    __half* tile = reinterpret_cast<__half*>(smc);      // [256][136]
    #pragma unroll
    for (int i = 0; i < 4; i++)
        #pragma unroll
        for (int j = 0; j < 8; j++) {
            const int m = wm * 64 + i * 16 + (lane >> 2);
            const int n = wn * 64 + j * 8 + (lane & 3) * 2;
            *reinterpret_cast<uint32_t*>(tile + m * 136 + n) =
                pack_h2(acc[i][j][0], acc[i][j][1]);
            *reinterpret_cast<uint32_t*>(tile + (m + 8) * 136 + n) =
                pack_h2(acc[i][j][2], acc[i][j][3]);
        }
    __syncthreads();
    {
        const int m = t;                                // all 256 rows
        const size_t k = (size_t)(b0 + m) * F_DIM + f;
        char* dst = reinterpret_cast<char*>(g_Wh) + (k >> 6) * 16384;
        const uint32_t kl = (uint32_t)(k & 63) * 256;
        const uint4* src = reinterpret_cast<const uint4*>(tile + m * 136);
        #pragma unroll
        for (int seg = 0; seg < 16; seg++)
            *reinterpret_cast<uint4*>(dst + SWZ256(kl + seg * 16)) = src[seg];
    }
}

// ---------------------------------------------------------------------------
// k_big: part[s][a,o] = sum_{k in split s} conn2d[a,k] * Wh[k,o]
// 512 threads (16 warps, 4x4), tile 128x128, KT=64. A: LDG fp32->cvt->STS.
// B: one cp.async.bulk (16KB pre-swizzled tile) per iteration + mbarrier ring.
// ---------------------------------------------------------------------------
__global__ void __launch_bounds__(512, 1) k_big(const float* __restrict__ conn) {
    extern __shared__ char smc[];
    const uint32_t sb = (uint32_t)__cvta_generic_to_shared(smc);
    const int t = threadIdx.x, lane = t & 31, wid = t >> 5;
    const int wm = wid >> 2, wn = wid & 3;
    const int m0    = blockIdx.x * 128;
    const int kbase = blockIdx.y * KC;
    const int gt0   = kbase / KT;             // first g_Wh tile index

    const uint32_t MB = sb + 98304;           // 4 mbarriers
    if (t == 0) {
        #pragma unroll
        for (int s = 0; s < 4; s++) mbar_init(MB + 8 * s, 1);
    }
    __syncthreads();

    auto issueB = [&](int it) {
        mbar_expect_tx(MB + 8 * (it & 3), 16384u);
        bulk_g2s(sb + 32768 + (it & 3) * 16384,
                 reinterpret_cast<const char*>(g_Wh) + (size_t)(gt0 + it) * 16384,
                 16384u, MB + 8 * (it & 3));
    };

    // A-side: thread -> row t>>2 (0..127), chunk t&3 (16 floats)
    const int aRowG  = t >> 2, aChunk = t & 3;
    const float* aSrc = conn + (size_t)(m0 + aRowG) * KBIG + kbase + aChunk * 16;
    const uint32_t aSts = aRowG * 128 + aChunk * 32;

    float4 rA[2][4];
    auto ldgA = [&](int it) {
        if (it < ITERS) {
            const float4* s4 = reinterpret_cast<const float4*>(aSrc + it * KT);
            #pragma unroll
            for (int q = 0; q < 4; q++) rA[it & 1][q] = s4[q];
        }
    };
    auto cvtA = [&](int it) {
        if (it < ITERS) {
            char* ab = smc + (it & 1) * 16384;
            const float4* r = rA[it & 1];
            #pragma unroll
            for (int q = 0; q < 4; q++)
                *reinterpret_cast<uint2*>(ab + SWZ128(aSts + q * 8)) =
                    make_uint2(pack_h2(r[q].x, r[q].y), pack_h2(r[q].z, r[q].w));
        }
    };

    if (t == 0) { issueB(0); issueB(1); issueB(2); }
    ldgA(0); ldgA(1);
    cvtA(0);
    __syncthreads();

    float acc[2][4][4];
    #pragma unroll
    for (int i = 0; i < 2; i++)
        #pragma unroll
        for (int j = 0; j < 4; j++)
            #pragma unroll
            for (int q = 0; q < 4; q++) acc[i][j][q] = 0.f;

    const int aRow = wm * 32 + (lane & 7) + ((lane >> 3) & 1) * 8;
    const int aKb  = ((lane >> 4) & 1) * 16;
    const int bK   = (lane & 7) + ((lane >> 3) & 1) * 8;
    const int bNb  = wn * 64 + ((lane >> 4) & 1) * 16;

    for (int it = 0; it < ITERS; ++it) {
        mbar_wait(MB + 8 * (it & 3), (uint32_t)(it >> 2) & 1u);
        ldgA(it + 2);

        const uint32_t ab = sb + (it & 1) * 16384;
        const uint32_t bb = sb + 32768 + (it & 3) * 16384;
        #pragma unroll
        for (int kc = 0; kc < 4; kc++) {
            uint32_t a[2][4], b[2][4];
            ldm_x4(a[0], ab + SWZ128(aRow * 128 + kc * 32 + aKb));
            ldm_x4(a[1], ab + SWZ128((aRow + 16) * 128 + kc * 32 + aKb));
            #pragma unroll
            for (int jj = 0; jj < 2; jj++)
                ldm_x4t(b[jj], bb + SWZ256((kc * 16 + bK) * 256 + bNb + jj * 32));
            #pragma unroll
            for (int i = 0; i < 2; i++)
                #pragma unroll
                for (int jj = 0; jj < 2; jj++) {
                    mma16(acc[i][jj * 2],     a[i], &b[jj][0]);
                    mma16(acc[i][jj * 2 + 1], a[i], &b[jj][2]);
                }
        }
        cvtA(it + 1);
        __syncthreads();
        if (t == 0 && it + 3 < ITERS) issueB(it + 3);
    }

    float* dst = g_part + (size_t)blockIdx.y * (A_DIM * O_DIM);
    #pragma unroll
    for (int i = 0; i < 2; i++)
        #pragma unroll
        for (int j = 0; j < 4; j++) {
            const int r0  = m0 + wm * 32 + i * 16 + (lane >> 2);
            const int col = wn * 32 + j * 8 + (lane & 3) * 2;
            *reinterpret_cast<float2*>(dst + (size_t)r0 * O_DIM + col) =
                make_float2(acc[i][j][0], acc[i][j][1]);
            *reinterpret_cast<float2*>(dst + (size_t)(r0 + 8) * O_DIM + col) =
                make_float2(acc[i][j][2], acc[i][j][3]);
        }
}

// ---------------------------------------------------------------------------
// k_reduce: out = sum_s part[s] + bond @ bias   (smem-staged, deterministic)
// ---------------------------------------------------------------------------
__global__ void __launch_bounds__(256) k_reduce(const float* __restrict__ bond,
                                                float* __restrict__ out) {
    __shared__ float bias_s[32 * 128];
    __shared__ float bond_s[64];
    const int t = threadIdx.x;
    const int idx = blockIdx.x * 256 + t;             // a*128 + o

    #pragma unroll
    for (int q = 0; q < 4; q++)
        reinterpret_cast<float4*>(bias_s)[q * 256 + t] =
            reinterpret_cast<const float4*>(g_bias)[q * 256 + t];
    if (t < 64) bond_s[t] = bond[(size_t)blockIdx.x * 64 + t];  // 2 a-rows x 32
    __syncthreads();

    float s = 0.f;
    #pragma unroll
    for (int sp = 0; sp < KSPLIT; sp++)
        s += g_part[(size_t)sp * (A_DIM * O_DIM) + idx];

    const int al = (t >> 7) & 1;                      // a within block
    const int o  = t & 127;
    #pragma unroll
    for (int fj = 0; fj < 32; fj++)
        s += bond_s[al * 32 + fj] * bias_s[fj * 128 + o];
    out[idx] = s;
}

// ---------------------------------------------------------------------------
extern "C" void kernel_launch(void* const* d_in, const int* in_sizes, int n_in,
                              void* d_out, int out_size) {
    const float* node = (const float*)d_in[0];   // (2048, 128)
    const float* conn = (const float*)d_in[1];   // (2048, 2048, 16)
    const float* bond = (const float*)d_in[2];   // (2048, 16, 2)
    const float* filt = (const float*)d_in[3];   // (128, 16, 130)
    float* out = (float*)d_out;                  // (2048, 128)
    (void)in_sizes; (void)n_in; (void)out_size;

    cudaFuncSetAttribute(k_wbuild, cudaFuncAttributeMaxDynamicSharedMemorySize, WB_SMEM);
    cudaFuncSetAttribute(k_big,    cudaFuncAttributeMaxDynamicSharedMemorySize, BIG_SMEM);

    k_prep<<<272, 256>>>(node, filt);
    k_wbuild<<<dim3(A_DIM / 256, F_DIM), 256, WB_SMEM>>>();
    k_big<<<dim3(A_DIM / 128, KSPLIT), 512, BIG_SMEM>>>(conn);
    k_reduce<<<(A_DIM * O_DIM) / 256, 256>>>(bond, out);
}

// round 7
// speedup vs baseline: 1.6577x; 1.1032x over previous
#include <cuda_runtime.h>
#include <cuda_fp16.h>
#include <cstdint>

// ---------------------------------------------------------------- constants
#define A_DIM    2048
#define D_DIM    128
#define O_DIM    128
#define F_DIM    16
#define KBIG     (A_DIM * F_DIM)      // 32768; k = b*16 + f (contiguous in conn)
#define FILT_ROW 2080                 // 16 * 130
#define KSPLIT   16
#define KC       (KBIG / KSPLIT)      // 2048
#define KT       32                   // k-depth per ktile in k_big
#define ITERS    (KC / KT)            // 64

#define SWZ128(x) ((x) ^ (((x) >> 3) & 0x70))   // 128B rows
#define SWZ256(x) ((x) ^ (((x) >> 4) & 0xF0))   // 256B rows

// k_big smem: A16 double buffer (2x16KB, rows padded to 128B) + B ring (4x8KB) + mbars
#define BIG_SMEM   (2 * 16384 + 4 * 8192 + 64)   // 65600 -> 2 CTAs/SM fits
#define WB_SMEM    98304

// scratch (__device__ globals: allocation-free rule)
// g_Wh TILED+SWIZZLED in 8KB tiles: tile g = k/32, within-tile byte offset
// = SWZ256((k&31)*256 + o*2) — exactly what k_big's B bulk-copy consumes.
__device__ __half g_Wh[(size_t)KBIG * O_DIM];            // 8 MB
__device__ __half g_nodeh[(size_t)A_DIM * D_DIM];        // node fp16
__device__ __half g_G[(size_t)D_DIM * A_DIM];            // G[d][f*128+o] = filt[o,f,d]
__device__ float  g_bias[32 * 128];                      // bias[fj][o] = filt[o,f,128+j]
__device__ float  g_part[(size_t)KSPLIT * A_DIM * O_DIM];   // 16 MB

// ---------------------------------------------------------------- ptx utils
__device__ __forceinline__ void cpa16s(uint32_t dst, const void* src) {
    asm volatile("cp.async.cg.shared.global [%0], [%1], 16;" :: "r"(dst), "l"(src));
}
__device__ __forceinline__ void cp_commit() { asm volatile("cp.async.commit_group;"); }
__device__ __forceinline__ void cp_wait0()  { asm volatile("cp.async.wait_group 0;"); }

__device__ __forceinline__ void mbar_init(uint32_t a, uint32_t cnt) {
    asm volatile("mbarrier.init.shared.b64 [%0], %1;" :: "r"(a), "r"(cnt) : "memory");
}
__device__ __forceinline__ void mbar_expect_tx(uint32_t a, uint32_t bytes) {
    asm volatile("mbarrier.arrive.expect_tx.shared.b64 _, [%0], %1;"
                 :: "r"(a), "r"(bytes) : "memory");
}
__device__ __forceinline__ void mbar_wait(uint32_t a, uint32_t parity) {
    asm volatile(
        "{\n"
        ".reg .pred P;\n"
        "LW%=:\n"
        "mbarrier.try_wait.parity.acquire.cta.shared::cta.b64 P, [%0], %1, 0x989680;\n"
        "@P bra LD%=;\n"
        "bra LW%=;\n"
        "LD%=:\n"
        "}" :: "r"(a), "r"(parity) : "memory");
}
__device__ __forceinline__ void bulk_g2s(uint32_t dst, const void* src,
                                         uint32_t bytes, uint32_t mbar) {
    asm volatile(
        "cp.async.bulk.shared::cluster.global.mbarrier::complete_tx::bytes "
        "[%0], [%1], %2, [%3];"
        :: "r"(dst), "l"(src), "r"(bytes), "r"(mbar) : "memory");
}

__device__ __forceinline__ void ldm_x4(uint32_t* r, uint32_t a) {
    asm volatile("ldmatrix.sync.aligned.m8n8.x4.shared.b16 {%0,%1,%2,%3}, [%4];"
        : "=r"(r[0]), "=r"(r[1]), "=r"(r[2]), "=r"(r[3]) : "r"(a));
}
__device__ __forceinline__ void ldm_x4t(uint32_t* r, uint32_t a) {
    asm volatile("ldmatrix.sync.aligned.m8n8.x4.trans.shared.b16 {%0,%1,%2,%3}, [%4];"
        : "=r"(r[0]), "=r"(r[1]), "=r"(r[2]), "=r"(r[3]) : "r"(a));
}
__device__ __forceinline__ void mma16(float* d, const uint32_t* a, const uint32_t* b) {
    asm volatile(
        "mma.sync.aligned.m16n8k16.row.col.f32.f16.f16.f32 "
        "{%0,%1,%2,%3}, {%4,%5,%6,%7}, {%8,%9}, {%0,%1,%2,%3};"
        : "+f"(d[0]), "+f"(d[1]), "+f"(d[2]), "+f"(d[3])
        : "r"(a[0]), "r"(a[1]), "r"(a[2]), "r"(a[3]), "r"(b[0]), "r"(b[1]));
}
__device__ __forceinline__ uint32_t pack_h2(float x, float y) {
    __half2 h = __floats2half2_rn(x, y);
    return *reinterpret_cast<uint32_t*>(&h);
}

// ---------------------------------------------------------------------------
// k_prep: g_G[d][f*128+o]=filt[o,f,d] fp16; g_nodeh=fp16(node); g_bias extract.
// ---------------------------------------------------------------------------
__global__ void __launch_bounds__(256) k_prep(const float* __restrict__ node,
                                              const float* __restrict__ filt) {
    __shared__ float sm[128][65];
    const int t = threadIdx.x;

    if (blockIdx.x < 16) {
        const int f = blockIdx.x;
        {
            const int o = t >> 1, j = t & 1;
            g_bias[f * 256 + j * 128 + o] = filt[(size_t)o * FILT_ROW + f * 130 + 128 + j];
        }
        #pragma unroll
        for (int p = 0; p < 2; p++) {
            const int o  = t >> 1;
            const int dq = (t & 1) * 32;
            const float* src = filt + (size_t)o * FILT_ROW + f * 130 + p * 64 + dq;
            #pragma unroll
            for (int q = 0; q < 16; q++) {
                float2 v = *reinterpret_cast<const float2*>(src + q * 2);
                sm[o][dq + q * 2]     = v.x;
                sm[o][dq + q * 2 + 1] = v.y;
            }
            __syncthreads();
            const int dl = t & 63, op = t >> 6;
            uint32_t* dst = reinterpret_cast<uint32_t*>(
                g_G + (size_t)(p * 64 + dl) * A_DIM + f * 128 + op * 32);
            #pragma unroll
            for (int q = 0; q < 16; q++)
                dst[q] = pack_h2(sm[op * 32 + q * 2][dl], sm[op * 32 + q * 2 + 1][dl]);
            __syncthreads();
        }
    } else {
        const int idx = (blockIdx.x - 16) * 256 + t;
        float4 v = reinterpret_cast<const float4*>(node)[idx];
        reinterpret_cast<uint2*>(g_nodeh)[idx] =
            make_uint2(pack_h2(v.x, v.y), pack_h2(v.z, v.w));
    }
}

// ---------------------------------------------------------------------------
// k_wbuild: W[k=b*16+f][o] = sum_d node_h[b,d] * G[d, f*128+o]
// GEMM 2048x2048x128, CTA 256x128, 8 warps. Output in 8KB-tile swizzled g_Wh.
// ---------------------------------------------------------------------------
__global__ void __launch_bounds__(256, 1) k_wbuild() {
    extern __shared__ char smc[];
    const uint32_t sb = (uint32_t)__cvta_generic_to_shared(smc);
    const int t = threadIdx.x, lane = t & 31, wid = t >> 5;
    const int wm = wid >> 1, wn = wid & 1;
    const int b0  = blockIdx.x * 256;
    const int fo0 = blockIdx.y * 128;
    const int f   = blockIdx.y;

    #pragma unroll
    for (int q = 0; q < 16; q++) {
        int c = q * 256 + t;
        int m = c >> 4, seg = c & 15;
        cpa16s(sb + SWZ256(m * 256 + seg * 16),
               g_nodeh + (size_t)(b0 + m) * D_DIM + seg * 8);
    }
    #pragma unroll
    for (int q = 0; q < 8; q++) {
        int c = q * 256 + t;
        int d = c >> 4, seg = c & 15;
        cpa16s(sb + 65536 + SWZ256(d * 256 + seg * 16),
               g_G + (size_t)d * A_DIM + fo0 + seg * 8);
    }
    cp_commit();
    cp_wait0();
    __syncthreads();

    float acc[4][8][4];
    #pragma unroll
    for (int i = 0; i < 4; i++)
        #pragma unroll
        for (int j = 0; j < 8; j++)
            #pragma unroll
            for (int q = 0; q < 4; q++) acc[i][j][q] = 0.f;

    const int aRow = wm * 64 + (lane & 7) + ((lane >> 3) & 1) * 8;
    const int aKb  = ((lane >> 4) & 1) * 16;
    const int bK   = (lane & 7) + ((lane >> 3) & 1) * 8;
    const int bNb  = (wn * 64 + ((lane >> 4) & 1) * 8) * 2;

    #pragma unroll
    for (int kc = 0; kc < 8; kc++) {
        uint32_t a[4][4], b[4][4];
        #pragma unroll
        for (int i = 0; i < 4; i++)
            ldm_x4(a[i], sb + SWZ256((aRow + i * 16) * 256 + kc * 32 + aKb));
        #pragma unroll
        for (int jj = 0; jj < 4; jj++)
            ldm_x4t(b[jj], sb + 65536 + SWZ256((kc * 16 + bK) * 256 + bNb + jj * 32));
        #pragma unroll
        for (int i = 0; i < 4; i++)
            #pragma unroll
            for (int jj = 0; jj < 4; jj++) {
                mma16(acc[i][jj * 2],     a[i], &b[jj][0]);
                mma16(acc[i][jj * 2 + 1], a[i], &b[jj][2]);
            }
    }

    __syncthreads();
    __half* tile = reinterpret_cast<__half*>(smc);      // [256][136]
    #pragma unroll
    for (int i = 0; i < 4; i++)
        #pragma unroll
        for (int j = 0; j < 8; j++) {
            const int m = wm * 64 + i * 16 + (lane >> 2);
            const int n = wn * 64 + j * 8 + (lane & 3) * 2;
            *reinterpret_cast<uint32_t*>(tile + m * 136 + n) =
                pack_h2(acc[i][j][0], acc[i][j][1]);
            *reinterpret_cast<uint32_t*>(tile + (m + 8) * 136 + n) =
                pack_h2(acc[i][j][2], acc[i][j][3]);
        }
    __syncthreads();
    {
        const int m = t;                                // all 256 rows
        const size_t k = (size_t)(b0 + m) * F_DIM + f;
        char* dst = reinterpret_cast<char*>(g_Wh) + (k >> 5) * 8192;   // 8KB tiles
        const uint32_t kl = (uint32_t)(k & 31) * 256;
        const uint4* src = reinterpret_cast<const uint4*>(tile + m * 136);
        #pragma unroll
        for (int seg = 0; seg < 16; seg++)
            *reinterpret_cast<uint4*>(dst + SWZ256(kl + seg * 16)) = src[seg];
    }
}

// ---------------------------------------------------------------------------
// k_big: part[s][a,o] = sum_{k in split s} conn2d[a,k] * Wh[k,o]
// 256 threads, 2 CTAs/SM, tile 128x128, KT=32. A: LDG fp32->cvt->STS (padded
// 128B rows). B: one 8KB cp.async.bulk per iteration + 4-slot mbarrier ring.
// ---------------------------------------------------------------------------
__global__ void __launch_bounds__(256, 2) k_big(const float* __restrict__ conn) {
    extern __shared__ char smc[];
    const uint32_t sb = (uint32_t)__cvta_generic_to_shared(smc);
    const int t = threadIdx.x, lane = t & 31, wid = t >> 5;
    const int wm = wid >> 1, wn = wid & 1;     // 4m x 2n, warp tile 32x64
    const int m0    = blockIdx.x * 128;
    const int kbase = blockIdx.y * KC;
    const int gt0   = kbase / KT;              // first 8KB g_Wh tile

    const uint32_t MB = sb + 65536;            // 4 mbarriers after A+B
    if (t == 0) {
        #pragma unroll
        for (int s = 0; s < 4; s++) mbar_init(MB + 8 * s, 1);
    }
    __syncthreads();

    auto issueB = [&](int it) {
        mbar_expect_tx(MB + 8 * (it & 3), 8192u);
        bulk_g2s(sb + 32768 + (it & 3) * 8192,
                 reinterpret_cast<const char*>(g_Wh) + (size_t)(gt0 + it) * 8192,
                 8192u, MB + 8 * (it & 3));
    };

    // A: row t>>1 (0..127), half t&1 (16 floats). A16 rows padded to 128B.
    const int aRowG = t >> 1, aHalf = t & 1;
    const float* aSrc = conn + (size_t)(m0 + aRowG) * KBIG + kbase + aHalf * 16;
    const uint32_t aSts = aRowG * 128 + aHalf * 32;

    float4 rA[2][4];
    auto ldgA = [&](int it) {
        if (it < ITERS) {
            const float4* s4 = reinterpret_cast<const float4*>(aSrc + it * KT);
            #pragma unroll
            for (int q = 0; q < 4; q++) rA[it & 1][q] = s4[q];
        }
    };
    auto cvtA = [&](int it) {
        if (it < ITERS) {
            char* ab = smc + (it & 1) * 16384;
            const float4* r = rA[it & 1];
            #pragma unroll
            for (int q = 0; q < 4; q++)
                *reinterpret_cast<uint2*>(ab + SWZ128(aSts + q * 8)) =
                    make_uint2(pack_h2(r[q].x, r[q].y), pack_h2(r[q].z, r[q].w));
        }
    };

    if (t == 0) { issueB(0); issueB(1); issueB(2); }
    ldgA(0); ldgA(1);
    cvtA(0);
    __syncthreads();

    float acc[2][8][4];
    #pragma unroll
    for (int i = 0; i < 2; i++)
        #pragma unroll
        for (int j = 0; j < 8; j++)
            #pragma unroll
            for (int q = 0; q < 4; q++) acc[i][j][q] = 0.f;

    const int aRow = wm * 32 + (lane & 7) + ((lane >> 3) & 1) * 8;
    const int aKb  = ((lane >> 4) & 1) * 16;
    const int bK   = (lane & 7) + ((lane >> 3) & 1) * 8;
    const int bNb  = (wn * 64 + ((lane >> 4) & 1) * 8) * 2;

    for (int it = 0; it < ITERS; ++it) {
        mbar_wait(MB + 8 * (it & 3), (uint32_t)(it >> 2) & 1u);
        ldgA(it + 2);

        const uint32_t ab = sb + (it & 1) * 16384;
        const uint32_t bb = sb + 32768 + (it & 3) * 8192;
        #pragma unroll
        for (int kc = 0; kc < 2; kc++) {
            uint32_t a[2][4], b[4][4];
            ldm_x4(a[0], ab + SWZ128(aRow * 128 + kc * 32 + aKb));
            ldm_x4(a[1], ab + SWZ128((aRow + 16) * 128 + kc * 32 + aKb));
            #pragma unroll
            for (int jj = 0; jj < 4; jj++)
                ldm_x4t(b[jj], bb + SWZ256((kc * 16 + bK) * 256 + bNb + jj * 32));
            #pragma unroll
            for (int i = 0; i < 2; i++)
                #pragma unroll
                for (int jj = 0; jj < 4; jj++) {
                    mma16(acc[i][jj * 2],     a[i], &b[jj][0]);
                    mma16(acc[i][jj * 2 + 1], a[i], &b[jj][2]);
                }
        }
        cvtA(it + 1);
        __syncthreads();
        if (t == 0 && it + 3 < ITERS) issueB(it + 3);
    }

    float* dst = g_part + (size_t)blockIdx.y * (A_DIM * O_DIM);
    #pragma unroll
    for (int i = 0; i < 2; i++)
        #pragma unroll
        for (int j = 0; j < 8; j++) {
            const int r0  = m0 + wm * 32 + i * 16 + (lane >> 2);
            const int col = wn * 64 + j * 8 + (lane & 3) * 2;
            *reinterpret_cast<float2*>(dst + (size_t)r0 * O_DIM + col) =
                make_float2(acc[i][j][0], acc[i][j][1]);
            *reinterpret_cast<float2*>(dst + (size_t)(r0 + 8) * O_DIM + col) =
                make_float2(acc[i][j][2], acc[i][j][3]);
        }
}

// ---------------------------------------------------------------------------
// k_reduce: out = sum_s part[s] + bond @ bias   (float4, deterministic)
// ---------------------------------------------------------------------------
__global__ void __launch_bounds__(256) k_reduce(const float* __restrict__ bond,
                                                float* __restrict__ out) {
    __shared__ float4 bias4[32][32];
    __shared__ float  bond_s[256];
    const int t = threadIdx.x;
    const int idx4 = blockIdx.x * 256 + t;            // float4 index over out

    #pragma unroll
    for (int q = 0; q < 4; q++)
        (&bias4[0][0])[q * 256 + t] = reinterpret_cast<const float4*>(g_bias)[q * 256 + t];
    bond_s[t] = bond[(size_t)blockIdx.x * 256 + t];   // 8 a-rows x 32
    __syncthreads();

    float4 s = make_float4(0.f, 0.f, 0.f, 0.f);
    #pragma unroll
    for (int sp = 0; sp < KSPLIT; sp++) {
        float4 v = reinterpret_cast<const float4*>(g_part)[(size_t)sp * 65536 + idx4];
        s.x += v.x; s.y += v.y; s.z += v.z; s.w += v.w;
    }

    const int al = t >> 5;                            // a within block (8)
    const int o4 = t & 31;                            // float4 col
    #pragma unroll
    for (int fj = 0; fj < 32; fj++) {
        const float w = bond_s[al * 32 + fj];
        const float4 b4 = bias4[fj][o4];
        s.x += w * b4.x; s.y += w * b4.y; s.z += w * b4.z; s.w += w * b4.w;
    }
    reinterpret_cast<float4*>(out)[idx4] = s;
}

// ---------------------------------------------------------------------------
extern "C" void kernel_launch(void* const* d_in, const int* in_sizes, int n_in,
                              void* d_out, int out_size) {
    const float* node = (const float*)d_in[0];   // (2048, 128)
    const float* conn = (const float*)d_in[1];   // (2048, 2048, 16)
    const float* bond = (const float*)d_in[2];   // (2048, 16, 2)
    const float* filt = (const float*)d_in[3];   // (128, 16, 130)
    float* out = (float*)d_out;                  // (2048, 128)
    (void)in_sizes; (void)n_in; (void)out_size;

    cudaFuncSetAttribute(k_wbuild, cudaFuncAttributeMaxDynamicSharedMemorySize, WB_SMEM);
    cudaFuncSetAttribute(k_big,    cudaFuncAttributeMaxDynamicSharedMemorySize, BIG_SMEM);

    k_prep<<<272, 256>>>(node, filt);
    k_wbuild<<<dim3(A_DIM / 256, F_DIM), 256, WB_SMEM>>>();
    k_big<<<dim3(A_DIM / 128, KSPLIT), 256, BIG_SMEM>>>(conn);
    k_reduce<<<256, 256>>>(bond, out);
}